// round 13
// baseline (speedup 1.0000x reference)
#include <cuda_runtime.h>
#include <cuda_fp16.h>
#include <cstdint>

// ---------------------------------------------------------------------------
// SpatialTransformer R12: R11 (mbarrier-pipelined fp16 GEMMs) + fp16
// ACCUMULATORS on the scores GEMM only (tests whether f16-acc HMMA runs 2x
// on sm_103's legacy tensor pipe; error budget ~+1.6e-4, analyzed).
//   cvt_all -> merged proj (Q,K,Vt) -> scores(f16acc) -> softmax -> At -> final
// ---------------------------------------------------------------------------

#define Cdim  1024
#define Bdim  4
#define SQdim 2048
#define SKVdim 2048
#define Mtot  (Bdim * SQdim)            // 8192

__device__ __half g_xh [(long long)Mtot * Cdim];
__device__ __half g_ceh[(long long)Mtot * Cdim];
__device__ __half g_Wqh[(long long)Cdim * Cdim];
__device__ __half g_Wkh[(long long)Cdim * Cdim];
__device__ __half g_Wvh[(long long)Cdim * Cdim];
__device__ __half g_Woh[(long long)Cdim * Cdim];
__device__ __half g_Qh [(long long)Mtot * Cdim];
__device__ __half g_Kh [(long long)Mtot * Cdim];
__device__ __half g_Vth[(long long)Cdim * Mtot];
__device__ __half g_Sh [(long long)Bdim * SQdim * SKVdim];
__device__ __half g_Ath[(long long)Mtot * Cdim];

__device__ __forceinline__ void mma_f16(float* d, const uint32_t* a, const uint32_t* b){
    asm volatile("mma.sync.aligned.m16n8k16.row.col.f32.f16.f16.f32 "
        "{%0,%1,%2,%3}, {%4,%5,%6,%7}, {%8,%9}, {%0,%1,%2,%3};"
        : "+f"(d[0]), "+f"(d[1]), "+f"(d[2]), "+f"(d[3])
        : "r"(a[0]), "r"(a[1]), "r"(a[2]), "r"(a[3]), "r"(b[0]), "r"(b[1]));
}
__device__ __forceinline__ void mma_f16h(uint32_t* d, const uint32_t* a, const uint32_t* b){
    asm volatile("mma.sync.aligned.m16n8k16.row.col.f16.f16.f16.f16 "
        "{%0,%1}, {%2,%3,%4,%5}, {%6,%7}, {%0,%1};"
        : "+r"(d[0]), "+r"(d[1])
        : "r"(a[0]), "r"(a[1]), "r"(a[2]), "r"(a[3]), "r"(b[0]), "r"(b[1]));
}

#define LDM4(r0,r1,r2,r3,addr) \
  asm volatile("ldmatrix.sync.aligned.m8n8.x4.shared.b16 {%0,%1,%2,%3}, [%4];" \
    : "=r"(r0),"=r"(r1),"=r"(r2),"=r"(r3) : "r"(addr))

#define CPA16(dst, src) \
  asm volatile("cp.async.cg.shared.global [%0], [%1], 16;" :: "r"(dst), "l"(src))

#define MBAR_INIT(a,c) \
  asm volatile("mbarrier.init.shared.b64 [%0], %1;" :: "r"(a), "r"(c) : "memory")
#define MBAR_ARRIVE(a) \
  asm volatile("mbarrier.arrive.shared.b64 _, [%0];" :: "r"(a) : "memory")
#define CPA_MBAR_ARRIVE(a) \
  asm volatile("cp.async.mbarrier.arrive.noinc.shared.b64 [%0];" :: "r"(a) : "memory")

#define MBAR_WAIT(a, ph) do { uint32_t _m=(a); uint32_t _p=(ph); uint32_t _d; \
  asm volatile("{\n\t.reg .pred p;\n\tmbarrier.try_wait.parity.acquire.cta.shared::cta.b64 p, [%1], %2;\n\tselp.b32 %0,1,0,p;\n\t}" \
      : "=r"(_d) : "r"(_m), "r"(_p) : "memory"); \
  if(!_d){ asm volatile("{\n\t.reg .pred P1;\n\tWL_%=:\n\tmbarrier.try_wait.parity.acquire.cta.shared::cta.b64 P1, [%0], %1, 0x989680;\n\t@P1 bra.uni WD_%=;\n\tbra.uni WL_%=;\n\tWD_%=:\n\t}" \
      :: "r"(_m), "r"(_p) : "memory"); } } while(0)

// Tile: 128 rows x (128B data + 16B pad) = 18432 B; A+B per stage = 36864 B
#define RSTR 144
#define TILEB 18432
#define BUFB  36864
#define MB_OFF (BUFB * 3)
#define SMEM_BYTES (MB_OFF + 64)       // 110656

// D[128x128] tile of scale*(A @ B^T) [+bias] [+Add].  Operands fp16, BK=64.
// FACC: fp16 accumulators (2x-rate hypothesis).  HOUT: half out, else float.
// MG3: grid (8,64,3) pointer-set dispatch (z=2 transposed+bias-M).
template<bool FACC, bool HOUT, bool BN_, bool ADD_, bool MG3>
__global__ __launch_bounds__(256, 2)
void gemm_k(const __half* __restrict__ A0, const __half* __restrict__ B0,
            const float* __restrict__ bias0, void* __restrict__ C0,
            const __half* __restrict__ A1, const __half* __restrict__ B1,
            const float* __restrict__ bias1, void* __restrict__ C1,
            const __half* __restrict__ A2, const __half* __restrict__ B2,
            const float* __restrict__ bias2, void* __restrict__ C2,
            const float* __restrict__ Add,
            int lda, int ldb, int ldc, int ldc2, int NK,
            long long sA, long long sB, long long sC, long long sAdd,
            float scale)
{
    extern __shared__ char smem[];
    uint32_t sbase;
    asm("{ .reg .u64 t; cvta.to.shared.u64 t, %1; cvt.u32.u64 %0, t; }"
        : "=r"(sbase) : "l"(smem));

    const int tid = threadIdx.x, wid = tid >> 5, lane = tid & 31;

    const __half* A;
    const __half* B;
    const float* bias;
    void* Csel;
    int m0, n0;
    bool biasM = false;
    if (MG3) {
        const int z = blockIdx.z;
        if (z == 0)      { A = A0; B = B0; bias = bias0; Csel = C0; }
        else if (z == 1) { A = A1; B = B1; bias = bias1; Csel = C1; }
        else             { A = A2; B = B2; bias = bias2; Csel = C2; }
        if (z == 2) { m0 = blockIdx.x * 128; n0 = blockIdx.y * 128; ldc = ldc2; biasM = true; }
        else        { m0 = blockIdx.y * 128; n0 = blockIdx.x * 128; }
    } else {
        A = A0 + (long long)blockIdx.z * sA;
        B = B0 + (long long)blockIdx.z * sB;
        bias = bias0;
        Csel = C0;
        m0 = blockIdx.y * 128; n0 = blockIdx.x * 128;
        if (ADD_) Add += (long long)blockIdx.z * sAdd;
    }

    // ---- mbarriers: full[s] (cp.async completion), empty[s] (consumers) ----
    const uint32_t mb = sbase + MB_OFF;
    if (tid == 0) {
        #pragma unroll
        for (int s = 0; s < 3; s++) {
            MBAR_INIT(mb + s * 8, 256);
            MBAR_INIT(mb + 24 + s * 8, 256);
        }
    }
    __syncthreads();

    // ---- cp.async loader: 2 threads per row, 4x16B chunks each ----
    const int lrow = tid >> 1;
    const int lhalf = tid & 1;
    const __half* ap = A + (long long)(m0 + lrow) * lda + lhalf * 32;
    const __half* bp = B + (long long)(n0 + lrow) * ldb + lhalf * 32;
    const uint32_t aSt = sbase + lrow * RSTR + lhalf * 64;
    const uint32_t bSt = sbase + TILEB + lrow * RSTR + lhalf * 64;

    // ---- warp mapping: 8 warps, 64x32 each ----
    const int wm = (wid & 1) * 64;
    const int wn = (wid >> 1) * 32;
    const int qr = lane >> 2, qc = lane & 3;
    uint32_t aF[4], bF[2];
    #pragma unroll
    for (int mi = 0; mi < 4; mi++)
        aF[mi] = sbase + (wm + mi * 16 + (lane & 15)) * RSTR + (lane >> 4) * 16;
    #pragma unroll
    for (int nt = 0; nt < 2; nt++)
        bF[nt] = sbase + TILEB +
                 (wn + nt * 16 + (lane & 7) + ((lane >> 4) << 3)) * RSTR +
                 ((lane >> 3) & 1) * 16;

    float acc[4][4][4];
    uint32_t hacc[4][4][2];
    if (FACC) {
        #pragma unroll
        for (int mi = 0; mi < 4; mi++)
            #pragma unroll
            for (int nj = 0; nj < 4; nj++) { hacc[mi][nj][0] = 0u; hacc[mi][nj][1] = 0u; }
    } else {
        #pragma unroll
        for (int mi = 0; mi < 4; mi++)
            #pragma unroll
            for (int nj = 0; nj < 4; nj++)
                #pragma unroll
                for (int j = 0; j < 4; j++) acc[mi][nj][j] = 0.f;
    }

    // ---- prologue: tiles 0,1 -> stages 0,1 ----
    #pragma unroll
    for (int i = 0; i < 4; i++) CPA16(aSt + i * 16, ap + i * 8);
    #pragma unroll
    for (int i = 0; i < 4; i++) CPA16(bSt + i * 16, bp + i * 8);
    CPA_MBAR_ARRIVE(mb + 0 * 8);
    if (NK > 1) {
        #pragma unroll
        for (int i = 0; i < 4; i++) CPA16(aSt + BUFB + i * 16, ap + 64 + i * 8);
        #pragma unroll
        for (int i = 0; i < 4; i++) CPA16(bSt + BUFB + i * 16, bp + 64 + i * 8);
        CPA_MBAR_ARRIVE(mb + 1 * 8);
    }

    int sc = 0, pc = 0;
    int sp = 2, pp = 1;
    for (int k = 0; k < NK; k++) {
        MBAR_WAIT(mb + sc * 8, pc);
        const uint32_t bo = sc * BUFB;
        #pragma unroll
        for (int s = 0; s < 4; s++) {
            uint32_t afr[4][4];
            #pragma unroll
            for (int mi = 0; mi < 4; mi++)
                LDM4(afr[mi][0], afr[mi][1], afr[mi][2], afr[mi][3],
                     aF[mi] + bo + s * 32);
            uint32_t bfr[4][2];
            #pragma unroll
            for (int nt = 0; nt < 2; nt++) {
                uint32_t t0, t1, t2, t3;
                LDM4(t0, t1, t2, t3, bF[nt] + bo + s * 32);
                bfr[nt * 2][0] = t0;     bfr[nt * 2][1] = t1;
                bfr[nt * 2 + 1][0] = t2; bfr[nt * 2 + 1][1] = t3;
            }
            #pragma unroll
            for (int mi = 0; mi < 4; mi++)
                #pragma unroll
                for (int nj = 0; nj < 4; nj++) {
                    if (FACC) mma_f16h(hacc[mi][nj], afr[mi], bfr[nj]);
                    else      mma_f16 (acc[mi][nj],  afr[mi], bfr[nj]);
                }
        }
        MBAR_ARRIVE(mb + 24 + sc * 8);
        if (++sc == 3) { sc = 0; pc ^= 1; }

        if (k + 2 < NK) {
            MBAR_WAIT(mb + 24 + sp * 8, pp);
            const int k0 = (k + 2) * 64;
            const uint32_t nb = sp * BUFB;
            #pragma unroll
            for (int i = 0; i < 4; i++) CPA16(aSt + nb + i * 16, ap + k0 + i * 8);
            #pragma unroll
            for (int i = 0; i < 4; i++) CPA16(bSt + nb + i * 16, bp + k0 + i * 8);
            CPA_MBAR_ARRIVE(mb + sp * 8);
            if (++sp == 3) { sp = 0; pp ^= 1; }
        }
    }

    // ---- epilogue ----
    #pragma unroll
    for (int mi = 0; mi < 4; mi++) {
        #pragma unroll
        for (int h = 0; h < 2; h++) {
            const long long gm = m0 + wm + mi * 16 + qr + h * 8;
            float bm = 0.f;
            if (MG3) { if (biasM) bm = bias[gm]; }
            #pragma unroll
            for (int nj = 0; nj < 4; nj++) {
                const int gn = n0 + wn + nj * 8 + qc * 2;
                float vx, vy;
                if (FACC) {
                    const float2 t = __half22float2(*(half2*)&hacc[mi][nj][h]);
                    vx = t.x * scale; vy = t.y * scale;
                } else {
                    vx = acc[mi][nj][h * 2 + 0] * scale;
                    vy = acc[mi][nj][h * 2 + 1] * scale;
                }
                if (MG3) {
                    if (biasM) { vx += bm; vy += bm; }
                    else { const float2 bb = *(const float2*)(bias + gn); vx += bb.x; vy += bb.y; }
                } else if (BN_) {
                    const float2 bb = *(const float2*)(bias + gn); vx += bb.x; vy += bb.y;
                }
                if (ADD_) {
                    const float2 ad = *(const float2*)(Add + gm * ldc + gn);
                    vx += ad.x; vy += ad.y;
                }
                if (HOUT) {
                    __half* Co = (__half*)Csel + (MG3 ? 0ll : (long long)blockIdx.z * sC);
                    *(half2*)(Co + gm * ldc + gn) = __floats2half2_rn(vx, vy);
                } else {
                    float* Co = (float*)Csel + (MG3 ? 0ll : (long long)blockIdx.z * sC);
                    *(float2*)(Co + gm * ldc + gn) = make_float2(vx, vy);
                }
            }
        }
    }
}

// One fused fp32->fp16 conversion over all six tensors (grid-stride)
#define ACT8 (Mtot * Cdim / 8)          // 1048576
#define W8   (Cdim * Cdim / 8)          // 131072
#define TOT8 (2 * ACT8 + 4 * W8)        // 2621440
__global__ __launch_bounds__(256)
void cvt_all(const float* __restrict__ x,  const float* __restrict__ ce,
             const float* __restrict__ Wq, const float* __restrict__ Wk,
             const float* __restrict__ Wv, const float* __restrict__ Wo,
             __half* __restrict__ xh,  __half* __restrict__ ceh,
             __half* __restrict__ Wqh, __half* __restrict__ Wkh,
             __half* __restrict__ Wvh, __half* __restrict__ Woh)
{
    for (int i = blockIdx.x * 256 + threadIdx.x; i < TOT8; i += gridDim.x * 256) {
        const float* s;
        __half* d;
        int j = i;
        if (j < ACT8)                 { s = x;  d = xh;  }
        else if ((j -= ACT8) < ACT8)  { s = ce; d = ceh; }
        else if ((j -= ACT8) < W8)    { s = Wq; d = Wqh; }
        else if ((j -= W8) < W8)      { s = Wk; d = Wkh; }
        else if ((j -= W8) < W8)      { s = Wv; d = Wvh; }
        else                          { j -= W8; s = Wo; d = Woh; }
        const float4 a = ((const float4*)s)[2 * j];
        const float4 b = ((const float4*)s)[2 * j + 1];
        uint4 o;
        half2 h;
        h = __floats2half2_rn(a.x, a.y); o.x = *(uint32_t*)&h;
        h = __floats2half2_rn(a.z, a.w); o.y = *(uint32_t*)&h;
        h = __floats2half2_rn(b.x, b.y); o.z = *(uint32_t*)&h;
        h = __floats2half2_rn(b.z, b.w); o.w = *(uint32_t*)&h;
        ((uint4*)d)[j] = o;
    }
}

// softmax over rows of 2048 halfs; 256 threads, 8 halfs/thread
__global__ __launch_bounds__(256)
void softmax_h(__half* __restrict__ S)
{
    uint4* p = (uint4*)(S + (long long)blockIdx.x * SKVdim);
    const int tid = threadIdx.x, wid = tid >> 5, lane = tid & 31;
    __shared__ float red[8];

    uint4 v = p[tid];
    float f[8];
    { float2 t;
      t = __half22float2(*(half2*)&v.x); f[0]=t.x; f[1]=t.y;
      t = __half22float2(*(half2*)&v.y); f[2]=t.x; f[3]=t.y;
      t = __half22float2(*(half2*)&v.z); f[4]=t.x; f[5]=t.y;
      t = __half22float2(*(half2*)&v.w); f[6]=t.x; f[7]=t.y; }

    float m = f[0];
    #pragma unroll
    for (int j = 1; j < 8; j++) m = fmaxf(m, f[j]);
    #pragma unroll
    for (int o = 16; o > 0; o >>= 1) m = fmaxf(m, __shfl_xor_sync(~0u, m, o));
    if (lane == 0) red[wid] = m;
    __syncthreads();
    m = red[0];
    #pragma unroll
    for (int w = 1; w < 8; w++) m = fmaxf(m, red[w]);
    __syncthreads();

    float s = 0.f;
    #pragma unroll
    for (int j = 0; j < 8; j++) { f[j] = __expf(f[j] - m); s += f[j]; }
    #pragma unroll
    for (int o = 16; o > 0; o >>= 1) s += __shfl_xor_sync(~0u, s, o);
    if (lane == 0) red[wid] = s;
    __syncthreads();
    s = red[0] + red[1] + red[2] + red[3] + red[4] + red[5] + red[6] + red[7];

    const float inv = 1.0f / s;
    half2 h;
    h = __floats2half2_rn(f[0]*inv, f[1]*inv); v.x = *(uint32_t*)&h;
    h = __floats2half2_rn(f[2]*inv, f[3]*inv); v.y = *(uint32_t*)&h;
    h = __floats2half2_rn(f[4]*inv, f[5]*inv); v.z = *(uint32_t*)&h;
    h = __floats2half2_rn(f[6]*inv, f[7]*inv); v.w = *(uint32_t*)&h;
    p[tid] = v;
}

extern "C" void kernel_launch(void* const* d_in, const int* in_sizes, int n_in,
                              void* d_out, int out_size)
{
    const float* x  = (const float*)d_in[0];
    const float* ce = (const float*)d_in[1];
    const float* Wq = (const float*)d_in[2];
    const float* bq = (const float*)d_in[3];
    const float* Wk = (const float*)d_in[4];
    const float* bk = (const float*)d_in[5];
    const float* Wv = (const float*)d_in[6];
    const float* bv = (const float*)d_in[7];
    const float* Wo = (const float*)d_in[8];
    const float* bo = (const float*)d_in[9];
    float* out = (float*)d_out;

    __half *xh, *ceh, *Wqh, *Wkh, *Wvh, *Woh, *Qh, *Kh, *Vth, *Sh, *Ath;
    cudaGetSymbolAddress((void**)&xh,  g_xh);
    cudaGetSymbolAddress((void**)&ceh, g_ceh);
    cudaGetSymbolAddress((void**)&Wqh, g_Wqh);
    cudaGetSymbolAddress((void**)&Wkh, g_Wkh);
    cudaGetSymbolAddress((void**)&Wvh, g_Wvh);
    cudaGetSymbolAddress((void**)&Woh, g_Woh);
    cudaGetSymbolAddress((void**)&Qh,  g_Qh);
    cudaGetSymbolAddress((void**)&Kh,  g_Kh);
    cudaGetSymbolAddress((void**)&Vth, g_Vth);
    cudaGetSymbolAddress((void**)&Sh,  g_Sh);
    cudaGetSymbolAddress((void**)&Ath, g_Ath);

    #define SETSM(KF) cudaFuncSetAttribute(KF, cudaFuncAttributeMaxDynamicSharedMemorySize, SMEM_BYTES)
    SETSM((gemm_k<false, true , false, false, true >));   // merged projections
    SETSM((gemm_k<true , true , false, false, false>));   // scores (fp16 acc)
    SETSM((gemm_k<false, true , false, true , false>));   // At (+residual)
    SETSM((gemm_k<false, false, true , false, false>));   // final

    dim3 blk(256);

    // 1: all dtype conversions
    cvt_all<<<1184, 256>>>(x, ce, Wq, Wk, Wv, Wo, xh, ceh, Wqh, Wkh, Wvh, Woh);

    // 2: merged z=0 Qh=xh@Wqh^T+bq; z=1 Kh=ceh@Wkh^T+bk; z=2 Vth=Wvh@ceh^T+bv
    gemm_k<false,true,false,false,true><<<dim3(Cdim/128, Mtot/128, 3), blk, SMEM_BYTES>>>(
        xh,  Wqh, bq, Qh,
        ceh, Wkh, bk, Kh,
        Wvh, ceh, bv, Vth,
        nullptr, Cdim, Cdim, Cdim, Mtot, Cdim/64, 0,0,0,0, 1.0f);
    // 3: Sh = (Qh @ Kh^T) / 32   (fp16 accumulators — the 2x-rate experiment)
    gemm_k<true,true,false,false,false><<<dim3(SKVdim/128, SQdim/128, Bdim), blk, SMEM_BYTES>>>(
        Qh, Kh, nullptr, Sh,
        nullptr, nullptr, nullptr, nullptr,
        nullptr, nullptr, nullptr, nullptr,
        nullptr, Cdim, Cdim, SKVdim, 0, Cdim/64,
        (long long)SQdim*Cdim, (long long)SKVdim*Cdim, (long long)SQdim*SKVdim, 0, 0.03125f);
    // 4: Ph = softmax(Sh)
    softmax_h<<<Bdim * SQdim, 256>>>(Sh);
    // 5: Ath = Ph @ Vth^T + x   (half out)
    gemm_k<false,true,false,true,false><<<dim3(Cdim/128, SQdim/128, Bdim), blk, SMEM_BYTES>>>(
        Sh, Vth, nullptr, Ath,
        nullptr, nullptr, nullptr, nullptr,
        nullptr, nullptr, nullptr, nullptr,
        x, SKVdim, Mtot, Cdim, 0, SKVdim/64,
        (long long)SQdim*SKVdim, (long long)SKVdim, (long long)SQdim*Cdim,
        (long long)SQdim*Cdim, 1.0f);
    // 6: out = Ath @ Woh^T + bo  (float out)
    gemm_k<false,false,true,false,false><<<dim3(Cdim/128, Mtot/128, 1), blk, SMEM_BYTES>>>(
        Ath, Woh, bo, out,
        nullptr, nullptr, nullptr, nullptr,
        nullptr, nullptr, nullptr, nullptr,
        nullptr, Cdim, Cdim, Cdim, 0, Cdim/64, 0,0,0,0, 1.0f);
}